// round 13
// baseline (speedup 1.0000x reference)
#include <cuda_runtime.h>
#include <stdint.h>
#include <math.h>

#define Bb 64
#define Nn 3
#define Tt 4096
#define Dd 64
#define Hh 128
#define ROWS ((size_t)Bb * Nn * Tt)   // 786432

typedef unsigned long long u64;

// -------- packed f32x2 helpers (Blackwell fma.rn.f32x2) --------
__device__ __forceinline__ u64 pk(float lo, float hi) {
    u64 r; asm("mov.b64 %0,{%1,%2};" : "=l"(r) : "f"(lo), "f"(hi)); return r;
}
__device__ __forceinline__ void upk(u64 v, float& lo, float& hi) {
    asm("mov.b64 {%0,%1},%2;" : "=f"(lo), "=f"(hi) : "l"(v));
}
__device__ __forceinline__ u64 f2fma(u64 a, u64 b, u64 c) {
    u64 d; asm("fma.rn.f32x2 %0,%1,%2,%3;" : "=l"(d) : "l"(a), "l"(b), "l"(c)); return d;
}
__device__ __forceinline__ float fex2(float x) {
    float r; asm("ex2.approx.f32 %0,%1;" : "=f"(r) : "f"(x)); return r;
}
__device__ __forceinline__ float frcp(float x) {
    float r; asm("rcp.approx.f32 %0,%1;" : "=f"(r) : "f"(x)); return r;
}
#define LOG2E 1.4426950408889634f
__device__ __forceinline__ float fsig(float x) { return frcp(1.f + fex2(-x * LOG2E)); }
__device__ __forceinline__ float ftanh_f(float x) { return 1.f - 2.f * frcp(1.f + fex2(x * (2.f * LOG2E))); }

// -------- scratch (static device globals; no runtime allocation) --------
__device__ float g_h  [(size_t)Bb * Nn * Tt * Hh];
__device__ float g_hsp[(size_t)Bb * Nn * Tt * Hh];
__device__ float g_gx [(size_t)Bb * Nn * Tt * 3 * Hh];

// ============================================================
// Kernel A: h = x @ gat_W + gat_b      (786432 x 64) @ (64 x 128)  [f32x2]
// ============================================================
__global__ __launch_bounds__(128) void gat_kernel(const float* __restrict__ x,
                                                  const float* __restrict__ W,
                                                  const float* __restrict__ bias)
{
    __shared__ __align__(16) float xs[16][64];
    const int c = threadIdx.x;
    const size_t r0 = (size_t)blockIdx.x * 16;

    {
        const float4* src = (const float4*)(x + r0 * Dd);
        float4* dst = (float4*)xs;
        dst[c]       = src[c];
        dst[c + 128] = src[c + 128];
    }
    u64 w2[32];
#pragma unroll
    for (int i = 0; i < 32; i++)
        w2[i] = pk(W[(2 * i) * Hh + c], W[(2 * i + 1) * Hh + c]);
    const float bv = bias[c];
    __syncthreads();

#pragma unroll 4
    for (int r = 0; r < 16; r++) {
        const ulonglong2* xr = (const ulonglong2*)xs[r];
        u64 a0 = 0ull, a1 = 0ull;
#pragma unroll
        for (int i = 0; i < 16; i++) {
            ulonglong2 xv = xr[i];
            a0 = f2fma(xv.x, w2[2 * i],     a0);
            a1 = f2fma(xv.y, w2[2 * i + 1], a1);
        }
        float l0, h0, l1, h1; upk(a0, l0, h0); upk(a1, l1, h1);
        g_h[(r0 + r) * Hh + c] = (l0 + h0) + (l1 + h1) + bv;
    }
}

// ============================================================
// Kernel B: attention + softmax + ELU + spatial LayerNorm
// Warp-per-timestep (proven in R9: ~290us faster than block version)
// ============================================================
__global__ __launch_bounds__(256) void attn_kernel(const float* __restrict__ a_src,
                                                   const float* __restrict__ a_dst,
                                                   const float* __restrict__ abias,
                                                   const float* __restrict__ sng,
                                                   const float* __restrict__ snb)
{
    const int lane = threadIdx.x & 31;
    const int wix  = blockIdx.x * 8 + (threadIdx.x >> 5);
    const int b = wix >> 12;
    const int t = wix & 4095;

    const float4 as4 = ((const float4*)a_src)[lane];
    const float4 ad4 = ((const float4*)a_dst)[lane];
    const float4 gw4 = ((const float4*)sng)[lane];
    const float4 gb4 = ((const float4*)snb)[lane];

    float bi[9];
#pragma unroll
    for (int q = 0; q < 9; q++) bi[q] = __ldg(abias + q);

    float4 hv[3];
#pragma unroll
    for (int j = 0; j < 3; j++)
        hv[j] = *(const float4*)(g_h + (((size_t)b * Nn + j) * Tt + t) * Hh + lane * 4);

    float v[6];
#pragma unroll
    for (int j = 0; j < 3; j++) {
        v[j]     = hv[j].x * as4.x + hv[j].y * as4.y + hv[j].z * as4.z + hv[j].w * as4.w;
        v[3 + j] = hv[j].x * ad4.x + hv[j].y * ad4.y + hv[j].z * ad4.z + hv[j].w * ad4.w;
    }
#pragma unroll
    for (int off = 16; off; off >>= 1) {
#pragma unroll
        for (int q = 0; q < 6; q++)
            v[q] += __shfl_xor_sync(0xffffffffu, v[q], off);
    }

    float4 o[3];
#pragma unroll
    for (int i = 0; i < 3; i++) {
        float sc[3];
#pragma unroll
        for (int j = 0; j < 3; j++) {
            float s = v[i] + v[3 + j];
            s = s > 0.f ? s : 0.2f * s;
            sc[j] = s + bi[i * 3 + j];
        }
        float mx = fmaxf(sc[0], fmaxf(sc[1], sc[2]));
        float e0 = __expf(sc[0] - mx), e1 = __expf(sc[1] - mx), e2 = __expf(sc[2] - mx);
        float inv = frcp(e0 + e1 + e2);
        e0 *= inv; e1 *= inv; e2 *= inv;
        float4 ov;
        ov.x = e0 * hv[0].x + e1 * hv[1].x + e2 * hv[2].x;
        ov.y = e0 * hv[0].y + e1 * hv[1].y + e2 * hv[2].y;
        ov.z = e0 * hv[0].z + e1 * hv[1].z + e2 * hv[2].z;
        ov.w = e0 * hv[0].w + e1 * hv[1].w + e2 * hv[2].w;
        ov.x = ov.x > 0.f ? ov.x : (__expf(ov.x) - 1.f);
        ov.y = ov.y > 0.f ? ov.y : (__expf(ov.y) - 1.f);
        ov.z = ov.z > 0.f ? ov.z : (__expf(ov.z) - 1.f);
        ov.w = ov.w > 0.f ? ov.w : (__expf(ov.w) - 1.f);
        o[i] = ov;
    }

    float st[6];
#pragma unroll
    for (int i = 0; i < 3; i++) {
        st[2*i]   = o[i].x + o[i].y + o[i].z + o[i].w;
        st[2*i+1] = o[i].x*o[i].x + o[i].y*o[i].y + o[i].z*o[i].z + o[i].w*o[i].w;
    }
#pragma unroll
    for (int off = 16; off; off >>= 1) {
#pragma unroll
        for (int q = 0; q < 6; q++)
            st[q] += __shfl_xor_sync(0xffffffffu, st[q], off);
    }
#pragma unroll
    for (int i = 0; i < 3; i++) {
        float mean = st[2*i] * (1.f / Hh);
        float var  = st[2*i+1] * (1.f / Hh) - mean * mean;
        float rstd = rsqrtf(var + 1e-5f);
        float4 r;
        r.x = (o[i].x - mean) * rstd * gw4.x + gb4.x;
        r.y = (o[i].y - mean) * rstd * gw4.y + gb4.y;
        r.z = (o[i].z - mean) * rstd * gw4.z + gb4.z;
        r.w = (o[i].w - mean) * rstd * gw4.w + gb4.w;
        *(float4*)(g_hsp + (((size_t)b * Nn + i) * Tt + t) * Hh + lane * 4) = r;
    }
}

// ============================================================
// Kernel C: gx = h_sp @ W_ih^T + b_ih   [f32x2]  (proven)
// ============================================================
__global__ __launch_bounds__(256) void gx_kernel(const float* __restrict__ Wih,
                                                 const float* __restrict__ bih)
{
    __shared__ __align__(16) float hs[32][128];
    __shared__ float ws[128][33];

    const int tid = threadIdx.x;
    const int gg  = tid & 127;
    const int rh  = tid >> 7;
    const int g0  = blockIdx.y * 128;
    const size_t r0 = (size_t)blockIdx.x * 32;

    {
        const float4* src = (const float4*)(g_hsp + r0 * Hh);
        float4* dst = (float4*)hs;
#pragma unroll
        for (int i = 0; i < 4; i++) dst[tid + 256 * i] = src[tid + 256 * i];
    }

    u64 acc[16];
#pragma unroll
    for (int i = 0; i < 16; i++) acc[i] = 0ull;

    for (int p = 0; p < 4; p++) {
        if (p) __syncthreads();
#pragma unroll
        for (int i = 0; i < 16; i++) {
            int idx = tid + 256 * i;
            int row = idx >> 5, k = idx & 31;
            ws[row][k] = Wih[(size_t)(g0 + row) * Hh + p * 32 + k];
        }
        __syncthreads();

        u64 w2[16];
#pragma unroll
        for (int i = 0; i < 16; i++)
            w2[i] = pk(ws[gg][2 * i], ws[gg][2 * i + 1]);

#pragma unroll
        for (int r = 0; r < 16; r++) {
            const ulonglong2* xr = (const ulonglong2*)(hs[rh * 16 + r] + p * 32);
#pragma unroll
            for (int i = 0; i < 8; i++) {
                ulonglong2 xv = xr[i];
                acc[r] = f2fma(xv.x, w2[2 * i],     acc[r]);
                acc[r] = f2fma(xv.y, w2[2 * i + 1], acc[r]);
            }
        }
    }

    const float bv = bih[g0 + gg];
#pragma unroll
    for (int r = 0; r < 16; r++) {
        size_t row = r0 + rh * 16 + r;
        float lo, hi; upk(acc[r], lo, hi);
        g_gx[row * 384 + g0 + gg] = lo + hi + bv;
    }
}

// ============================================================
// Kernel D: GRU. 96 blocks x 768 threads (24 warps, 2x occupancy).
// Thread u owns ONE (row, K-half) task: 32 u64 weight regs (~80 regs tot).
// Same proven R5 dataflow: matvec partials -> px -> gates (u<256).
// ============================================================
__global__ __launch_bounds__(768, 1) void gru_kernel(const float* __restrict__ Whh,
                                                     const float* __restrict__ bhh,
                                                     float* __restrict__ out)
{
    const int u = threadIdx.x;                  // 0..767
    const int sA = blockIdx.x * 2;

    const int half = (u >= 384) ? 1 : 0;
    const int row  = u - half * 384;            // 0..383

    __shared__ __align__(16) float hbuf[2][128];
    __shared__ u64 px[2][384];                  // [half][row] -> (partA, partB)

    // register-resident weights: K-half of row (64 floats = 32 u64)
    u64 w[32];
    {
        const u64* wr = (const u64*)(Whh + (size_t)row * Hh + half * 64);
#pragma unroll
        for (int i = 0; i < 32; i++) w[i] = wr[i];
    }
    const float bh = half ? 0.f : bhh[row];     // bias folded into half-0 partial

    // gate mapping (u < 256)
    const int gq = u & 127;
    const int gs = (u >> 7) & 1;

    if (u < 128) { hbuf[0][u] = 0.f; hbuf[1][u] = 0.f; }

    const float* gxp = g_gx + (size_t)(sA + gs) * Tt * 384;
    float* op = out + (size_t)(sA + gs) * Tt * Hh;
    const float* pxf = (const float*)px;        // [(half*384+row)*2 + seq]

    float fr = 0.f, fz = 0.f, fn = 0.f;
    if (u < 256) {
        fr = __ldg(gxp + gq);
        fz = __ldg(gxp + gq + 128);
        fn = __ldg(gxp + gq + 256);
    }
    __syncthreads();

    for (int t = 0; t < Tt; t++) {
        // matvec partial over this thread's K-half, both sequences
        const ulonglong2* hA2 = (const ulonglong2*)(hbuf[0] + half * 64);
        const ulonglong2* hB2 = (const ulonglong2*)(hbuf[1] + half * 64);
        u64 aA = 0ull, aB = 0ull;
#pragma unroll
        for (int i = 0; i < 16; i++) {
            ulonglong2 ha = hA2[i];
            ulonglong2 hb = hB2[i];
            aA = f2fma(w[2*i],   ha.x, aA);
            aB = f2fma(w[2*i],   hb.x, aB);
            aA = f2fma(w[2*i+1], ha.y, aA);
            aB = f2fma(w[2*i+1], hb.y, aB);
        }
        float lo, hi;
        upk(aA, lo, hi); const float pA = lo + hi + bh;
        upk(aB, lo, hi); const float pB = lo + hi + bh;
        px[half][row] = pk(pA, pB);
        __syncthreads();

        if (u < 256) {
            const float ghr = pxf[(gq       ) * 2 + gs] + pxf[(384 + gq       ) * 2 + gs];
            const float ghz = pxf[(gq + 128 ) * 2 + gs] + pxf[(384 + gq + 128 ) * 2 + gs];
            const float ghn = pxf[(gq + 256 ) * 2 + gs] + pxf[(384 + gq + 256 ) * 2 + gs];
            const float r = fsig(fr + ghr);
            const float z = fsig(fz + ghz);
            const float n = ftanh_f(fn + r * ghn);
            const float hp = hbuf[gs][gq];
            const float hnew = (1.f - z) * n + z * hp;
            hbuf[gs][gq] = hnew;
            op[(size_t)t * Hh + gq] = hnew;

            const float* nx = gxp + (size_t)((t + 1 < Tt) ? t + 1 : t) * 384;
            fr = __ldg(nx + gq);
            fz = __ldg(nx + gq + 128);
            fn = __ldg(nx + gq + 256);
        }
        __syncthreads();
    }
}

// ============================================================
// Kernel E: temporal LayerNorm, in-place. One warp per row.
// ============================================================
__global__ __launch_bounds__(256) void tln_kernel(float* __restrict__ out,
                                                  const float* __restrict__ g,
                                                  const float* __restrict__ b)
{
    const int warp = threadIdx.x >> 5, lane = threadIdx.x & 31;
    const size_t row = (size_t)blockIdx.x * 8 + warp;
    float4* p = (float4*)(out + row * Hh);
    float4 v = p[lane];
    float s = v.x + v.y + v.z + v.w;
    float q = v.x * v.x + v.y * v.y + v.z * v.z + v.w * v.w;
#pragma unroll
    for (int off = 16; off; off >>= 1) {
        s += __shfl_xor_sync(0xffffffffu, s, off);
        q += __shfl_xor_sync(0xffffffffu, q, off);
    }
    const float mean = s * (1.f / Hh);
    const float var  = q * (1.f / Hh) - mean * mean;
    const float rstd = rsqrtf(var + 1e-5f);
    const float4 gv = ((const float4*)g)[lane];
    const float4 bv = ((const float4*)b)[lane];
    v.x = (v.x - mean) * rstd * gv.x + bv.x;
    v.y = (v.y - mean) * rstd * gv.y + bv.y;
    v.z = (v.z - mean) * rstd * gv.z + bv.z;
    v.w = (v.w - mean) * rstd * gv.w + bv.w;
    p[lane] = v;
}

// ============================================================
extern "C" void kernel_launch(void* const* d_in, const int* in_sizes, int n_in,
                              void* d_out, int out_size)
{
    const float* x      = (const float*)d_in[0];
    const float* gat_W  = (const float*)d_in[1];
    const float* gat_b  = (const float*)d_in[2];
    const float* a_src  = (const float*)d_in[3];
    const float* a_dst  = (const float*)d_in[4];
    const float* abias  = (const float*)d_in[5];
    const float* sn_g   = (const float*)d_in[6];
    const float* sn_b   = (const float*)d_in[7];
    const float* W_ih   = (const float*)d_in[8];
    const float* W_hh   = (const float*)d_in[9];
    const float* b_ih   = (const float*)d_in[10];
    const float* b_hh   = (const float*)d_in[11];
    const float* tn_g   = (const float*)d_in[12];
    const float* tn_b   = (const float*)d_in[13];
    float* out = (float*)d_out;

    gat_kernel<<<ROWS / 16, 128>>>(x, gat_W, gat_b);
    attn_kernel<<<(Bb * Tt) / 8, 256>>>(a_src, a_dst, abias, sn_g, sn_b);
    gx_kernel<<<dim3(ROWS / 32, 3), 256>>>(W_ih, b_ih);
    gru_kernel<<<Bb * Nn / 2, 768>>>(W_hh, b_hh, out);
    tln_kernel<<<ROWS / 8, 256>>>(out, tn_g, tn_b);
}

// round 14
// speedup vs baseline: 1.1020x; 1.1020x over previous
#include <cuda_runtime.h>
#include <stdint.h>
#include <math.h>

#define Bb 64
#define Nn 3
#define Tt 4096
#define Dd 64
#define Hh 128
#define ROWS ((size_t)Bb * Nn * Tt)   // 786432

typedef unsigned long long u64;

// -------- packed f32x2 helpers (Blackwell fma.rn.f32x2) --------
__device__ __forceinline__ u64 pk(float lo, float hi) {
    u64 r; asm("mov.b64 %0,{%1,%2};" : "=l"(r) : "f"(lo), "f"(hi)); return r;
}
__device__ __forceinline__ void upk(u64 v, float& lo, float& hi) {
    asm("mov.b64 {%0,%1},%2;" : "=f"(lo), "=f"(hi) : "l"(v));
}
__device__ __forceinline__ u64 f2fma(u64 a, u64 b, u64 c) {
    u64 d; asm("fma.rn.f32x2 %0,%1,%2,%3;" : "=l"(d) : "l"(a), "l"(b), "l"(c)); return d;
}
__device__ __forceinline__ float fex2(float x) {
    float r; asm("ex2.approx.f32 %0,%1;" : "=f"(r) : "f"(x)); return r;
}
__device__ __forceinline__ float frcp(float x) {
    float r; asm("rcp.approx.f32 %0,%1;" : "=f"(r) : "f"(x)); return r;
}
#define LOG2E 1.4426950408889634f
__device__ __forceinline__ float fsig(float x) { return frcp(1.f + fex2(-x * LOG2E)); }
__device__ __forceinline__ float ftanh_f(float x) { return 1.f - 2.f * frcp(1.f + fex2(x * (2.f * LOG2E))); }

// -------- scratch (static device globals; no runtime allocation) --------
__device__ float g_h  [(size_t)Bb * Nn * Tt * Hh];
__device__ float g_hsp[(size_t)Bb * Nn * Tt * Hh];
__device__ float g_gx [(size_t)Bb * Nn * Tt * 3 * Hh];
__device__ unsigned g_prog[96];     // per-seq-pair GRU progress (timesteps done)

// ============================================================
// Kernel A: h = x @ gat_W + gat_b      (786432 x 64) @ (64 x 128)  [f32x2]
// ============================================================
__global__ __launch_bounds__(128) void gat_kernel(const float* __restrict__ x,
                                                  const float* __restrict__ W,
                                                  const float* __restrict__ bias)
{
    __shared__ __align__(16) float xs[16][64];
    const int c = threadIdx.x;
    const size_t r0 = (size_t)blockIdx.x * 16;

    {
        const float4* src = (const float4*)(x + r0 * Dd);
        float4* dst = (float4*)xs;
        dst[c]       = src[c];
        dst[c + 128] = src[c + 128];
    }
    u64 w2[32];
#pragma unroll
    for (int i = 0; i < 32; i++)
        w2[i] = pk(W[(2 * i) * Hh + c], W[(2 * i + 1) * Hh + c]);
    const float bv = bias[c];
    __syncthreads();

#pragma unroll 4
    for (int r = 0; r < 16; r++) {
        const ulonglong2* xr = (const ulonglong2*)xs[r];
        u64 a0 = 0ull, a1 = 0ull;
#pragma unroll
        for (int i = 0; i < 16; i++) {
            ulonglong2 xv = xr[i];
            a0 = f2fma(xv.x, w2[2 * i],     a0);
            a1 = f2fma(xv.y, w2[2 * i + 1], a1);
        }
        float l0, h0, l1, h1; upk(a0, l0, h0); upk(a1, l1, h1);
        g_h[(r0 + r) * Hh + c] = (l0 + h0) + (l1 + h1) + bv;
    }
}

// ============================================================
// Kernel B: attention + softmax + ELU + spatial LayerNorm
// Warp-per-timestep (proven fastest in R9)
// ============================================================
__global__ __launch_bounds__(256) void attn_kernel(const float* __restrict__ a_src,
                                                   const float* __restrict__ a_dst,
                                                   const float* __restrict__ abias,
                                                   const float* __restrict__ sng,
                                                   const float* __restrict__ snb)
{
    const int lane = threadIdx.x & 31;
    const int wix  = blockIdx.x * 8 + (threadIdx.x >> 5);
    const int b = wix >> 12;
    const int t = wix & 4095;

    const float4 as4 = ((const float4*)a_src)[lane];
    const float4 ad4 = ((const float4*)a_dst)[lane];
    const float4 gw4 = ((const float4*)sng)[lane];
    const float4 gb4 = ((const float4*)snb)[lane];

    float bi[9];
#pragma unroll
    for (int q = 0; q < 9; q++) bi[q] = __ldg(abias + q);

    float4 hv[3];
#pragma unroll
    for (int j = 0; j < 3; j++)
        hv[j] = *(const float4*)(g_h + (((size_t)b * Nn + j) * Tt + t) * Hh + lane * 4);

    float v[6];
#pragma unroll
    for (int j = 0; j < 3; j++) {
        v[j]     = hv[j].x * as4.x + hv[j].y * as4.y + hv[j].z * as4.z + hv[j].w * as4.w;
        v[3 + j] = hv[j].x * ad4.x + hv[j].y * ad4.y + hv[j].z * ad4.z + hv[j].w * ad4.w;
    }
#pragma unroll
    for (int off = 16; off; off >>= 1) {
#pragma unroll
        for (int q = 0; q < 6; q++)
            v[q] += __shfl_xor_sync(0xffffffffu, v[q], off);
    }

    float4 o[3];
#pragma unroll
    for (int i = 0; i < 3; i++) {
        float sc[3];
#pragma unroll
        for (int j = 0; j < 3; j++) {
            float s = v[i] + v[3 + j];
            s = s > 0.f ? s : 0.2f * s;
            sc[j] = s + bi[i * 3 + j];
        }
        float mx = fmaxf(sc[0], fmaxf(sc[1], sc[2]));
        float e0 = __expf(sc[0] - mx), e1 = __expf(sc[1] - mx), e2 = __expf(sc[2] - mx);
        float inv = frcp(e0 + e1 + e2);
        e0 *= inv; e1 *= inv; e2 *= inv;
        float4 ov;
        ov.x = e0 * hv[0].x + e1 * hv[1].x + e2 * hv[2].x;
        ov.y = e0 * hv[0].y + e1 * hv[1].y + e2 * hv[2].y;
        ov.z = e0 * hv[0].z + e1 * hv[1].z + e2 * hv[2].z;
        ov.w = e0 * hv[0].w + e1 * hv[1].w + e2 * hv[2].w;
        ov.x = ov.x > 0.f ? ov.x : (__expf(ov.x) - 1.f);
        ov.y = ov.y > 0.f ? ov.y : (__expf(ov.y) - 1.f);
        ov.z = ov.z > 0.f ? ov.z : (__expf(ov.z) - 1.f);
        ov.w = ov.w > 0.f ? ov.w : (__expf(ov.w) - 1.f);
        o[i] = ov;
    }

    float st[6];
#pragma unroll
    for (int i = 0; i < 3; i++) {
        st[2*i]   = o[i].x + o[i].y + o[i].z + o[i].w;
        st[2*i+1] = o[i].x*o[i].x + o[i].y*o[i].y + o[i].z*o[i].z + o[i].w*o[i].w;
    }
#pragma unroll
    for (int off = 16; off; off >>= 1) {
#pragma unroll
        for (int q = 0; q < 6; q++)
            st[q] += __shfl_xor_sync(0xffffffffu, st[q], off);
    }
#pragma unroll
    for (int i = 0; i < 3; i++) {
        float mean = st[2*i] * (1.f / Hh);
        float var  = st[2*i+1] * (1.f / Hh) - mean * mean;
        float rstd = rsqrtf(var + 1e-5f);
        float4 r;
        r.x = (o[i].x - mean) * rstd * gw4.x + gb4.x;
        r.y = (o[i].y - mean) * rstd * gw4.y + gb4.y;
        r.z = (o[i].z - mean) * rstd * gw4.z + gb4.z;
        r.w = (o[i].w - mean) * rstd * gw4.w + gb4.w;
        *(float4*)(g_hsp + (((size_t)b * Nn + i) * Tt + t) * Hh + lane * 4) = r;
    }
}

// ============================================================
// Kernel C: gx = h_sp @ W_ih^T + b_ih   [f32x2]  (proven)
// Also resets g_prog (runs strictly before the fused GRU kernel).
// ============================================================
__global__ __launch_bounds__(256) void gx_kernel(const float* __restrict__ Wih,
                                                 const float* __restrict__ bih)
{
    __shared__ __align__(16) float hs[32][128];
    __shared__ float ws[128][33];

    const int tid = threadIdx.x;
    if (blockIdx.y == 0 && blockIdx.x < 96 && tid == 0)
        *((volatile unsigned*)&g_prog[blockIdx.x]) = 0u;

    const int gg  = tid & 127;
    const int rh  = tid >> 7;
    const int g0  = blockIdx.y * 128;
    const size_t r0 = (size_t)blockIdx.x * 32;

    {
        const float4* src = (const float4*)(g_hsp + r0 * Hh);
        float4* dst = (float4*)hs;
#pragma unroll
        for (int i = 0; i < 4; i++) dst[tid + 256 * i] = src[tid + 256 * i];
    }

    u64 acc[16];
#pragma unroll
    for (int i = 0; i < 16; i++) acc[i] = 0ull;

    for (int p = 0; p < 4; p++) {
        if (p) __syncthreads();
#pragma unroll
        for (int i = 0; i < 16; i++) {
            int idx = tid + 256 * i;
            int row = idx >> 5, k = idx & 31;
            ws[row][k] = Wih[(size_t)(g0 + row) * Hh + p * 32 + k];
        }
        __syncthreads();

        u64 w2[16];
#pragma unroll
        for (int i = 0; i < 16; i++)
            w2[i] = pk(ws[gg][2 * i], ws[gg][2 * i + 1]);

#pragma unroll
        for (int r = 0; r < 16; r++) {
            const ulonglong2* xr = (const ulonglong2*)(hs[rh * 16 + r] + p * 32);
#pragma unroll
            for (int i = 0; i < 8; i++) {
                ulonglong2 xv = xr[i];
                acc[r] = f2fma(xv.x, w2[2 * i],     acc[r]);
                acc[r] = f2fma(xv.y, w2[2 * i + 1], acc[r]);
            }
        }
    }

    const float bv = bih[g0 + gg];
#pragma unroll
    for (int r = 0; r < 16; r++) {
        size_t row = r0 + rh * 16 + r;
        float lo, hi; upk(acc[r], lo, hi);
        g_gx[row * 384 + g0 + gg] = lo + hi + bv;
    }
}

// ============================================================
// Kernel D (fused): 148 blocks x 384 threads.
//   blocks 0..95  : GRU (exact R5 core, 2 seqs/block) + progress publish
//   blocks 96..147: persistent temporal-LN consumers on `out`
// One-way dependency (LN waits on GRU) -> deadlock-free.
// ============================================================
__global__ __launch_bounds__(384, 1) void gru_tln_kernel(const float* __restrict__ Whh,
                                                         const float* __restrict__ bhh,
                                                         const float* __restrict__ tng,
                                                         const float* __restrict__ tnb,
                                                         float* __restrict__ out)
{
    const int u = threadIdx.x;                  // 0..383

    if (blockIdx.x < 96) {
        // ---------------- GRU producer (exact R5 core) ----------------
        const int sA = blockIdx.x * 2;

        const int half  = (u >= 192) ? 1 : 0;
        const int rbase = u - half * 192;       // 0..191
        const int r1 = rbase, r2 = rbase + 192;

        __shared__ __align__(16) float hbuf[2][128];
        __shared__ u64 px[2][384];              // [half][row] -> (partA, partB)

        u64 w1[32], w2r[32];
        {
            const u64* p1 = (const u64*)(Whh + (size_t)r1 * Hh + half * 64);
            const u64* p2 = (const u64*)(Whh + (size_t)r2 * Hh + half * 64);
#pragma unroll
            for (int i = 0; i < 32; i++) { w1[i] = p1[i]; w2r[i] = p2[i]; }
        }
        const float bh1 = half ? 0.f : bhh[r1];
        const float bh2 = half ? 0.f : bhh[r2];

        const int gq = u & 127;
        const int gs = (u >> 7) & 1;

        if (u < 128) { hbuf[0][u] = 0.f; hbuf[1][u] = 0.f; }

        const float* gxp = g_gx + (size_t)(sA + gs) * Tt * 384;
        float* op = out + (size_t)(sA + gs) * Tt * Hh;
        const float* pxf = (const float*)px;

        float fr = 0.f, fz = 0.f, fn = 0.f;
        if (u < 256) {
            fr = __ldg(gxp + gq);
            fz = __ldg(gxp + gq + 128);
            fn = __ldg(gxp + gq + 256);
        }
        __syncthreads();

        for (int t = 0; t < Tt; t++) {
            const ulonglong2* hA2 = (const ulonglong2*)(hbuf[0] + half * 64);
            const ulonglong2* hB2 = (const ulonglong2*)(hbuf[1] + half * 64);
            u64 a1A = 0ull, a2A = 0ull, a1B = 0ull, a2B = 0ull;
#pragma unroll
            for (int i = 0; i < 16; i++) {
                ulonglong2 ha = hA2[i];
                ulonglong2 hb = hB2[i];
                a1A = f2fma(w1[2*i],    ha.x, a1A);
                a2A = f2fma(w2r[2*i],   ha.x, a2A);
                a1B = f2fma(w1[2*i],    hb.x, a1B);
                a2B = f2fma(w2r[2*i],   hb.x, a2B);
                a1A = f2fma(w1[2*i+1],  ha.y, a1A);
                a2A = f2fma(w2r[2*i+1], ha.y, a2A);
                a1B = f2fma(w1[2*i+1],  hb.y, a1B);
                a2B = f2fma(w2r[2*i+1], hb.y, a2B);
            }
            float lo, hi;
            upk(a1A, lo, hi); const float p1A = lo + hi + bh1;
            upk(a2A, lo, hi); const float p2A = lo + hi + bh2;
            upk(a1B, lo, hi); const float p1B = lo + hi + bh1;
            upk(a2B, lo, hi); const float p2B = lo + hi + bh2;
            px[half][r1] = pk(p1A, p1B);
            px[half][r2] = pk(p2A, p2B);
            __syncthreads();

            if (u < 256) {
                const float ghr = pxf[(gq       ) * 2 + gs] + pxf[(384 + gq       ) * 2 + gs];
                const float ghz = pxf[(gq + 128 ) * 2 + gs] + pxf[(384 + gq + 128 ) * 2 + gs];
                const float ghn = pxf[(gq + 256 ) * 2 + gs] + pxf[(384 + gq + 256 ) * 2 + gs];
                const float r = fsig(fr + ghr);
                const float z = fsig(fz + ghz);
                const float n = ftanh_f(fn + r * ghn);
                const float hp = hbuf[gs][gq];
                const float hnew = (1.f - z) * n + z * hp;
                hbuf[gs][gq] = hnew;
                op[(size_t)t * Hh + gq] = hnew;

                const float* nx = gxp + (size_t)((t + 1 < Tt) ? t + 1 : t) * 384;
                fr = __ldg(nx + gq);
                fz = __ldg(nx + gq + 128);
                fn = __ldg(nx + gq + 256);
            }
            __syncthreads();

            // publish progress every 256 steps (release: fence -> bar -> flag)
            if ((t & 255) == 255) {
                __threadfence();
                __syncthreads();
                if (u == 0)
                    *((volatile unsigned*)&g_prog[blockIdx.x]) = (unsigned)(t + 1);
            }
        }
    } else {
        // ---------------- temporal-LN consumers ----------------
        const int j = blockIdx.x - 96;          // 0..51
        const int warp = u >> 5, lane = u & 31;
        const float4 gv = ((const float4*)tng)[lane];
        const float4 bv = ((const float4*)tnb)[lane];

        for (int item = j; item < 96 * 16; item += 52) {
            const int m = item >> 4;            // seq pair
            const int k = item & 15;            // 256-step chunk
            if (u == 0) {
                while (*((volatile unsigned*)&g_prog[m]) < (unsigned)((k + 1) * 256))
                    __nanosleep(256);
            }
            __syncthreads();
            __threadfence();                    // acquire

            for (int r = warp; r < 512; r += 12) {
                const int s = 2 * m + (r >> 8);
                const int t = k * 256 + (r & 255);
                float* p = out + ((size_t)s * Tt + t) * Hh + lane * 4;
                float4 v = __ldcg((const float4*)p);
                float sm = v.x + v.y + v.z + v.w;
                float sq = v.x*v.x + v.y*v.y + v.z*v.z + v.w*v.w;
#pragma unroll
                for (int off = 16; off; off >>= 1) {
                    sm += __shfl_xor_sync(0xffffffffu, sm, off);
                    sq += __shfl_xor_sync(0xffffffffu, sq, off);
                }
                const float mean = sm * (1.f / Hh);
                const float var  = sq * (1.f / Hh) - mean * mean;
                const float rstd = rsqrtf(var + 1e-5f);
                float4 o;
                o.x = (v.x - mean) * rstd * gv.x + bv.x;
                o.y = (v.y - mean) * rstd * gv.y + bv.y;
                o.z = (v.z - mean) * rstd * gv.z + bv.z;
                o.w = (v.w - mean) * rstd * gv.w + bv.w;
                *(float4*)p = o;
            }
        }
    }
}

// ============================================================
extern "C" void kernel_launch(void* const* d_in, const int* in_sizes, int n_in,
                              void* d_out, int out_size)
{
    const float* x      = (const float*)d_in[0];
    const float* gat_W  = (const float*)d_in[1];
    const float* gat_b  = (const float*)d_in[2];
    const float* a_src  = (const float*)d_in[3];
    const float* a_dst  = (const float*)d_in[4];
    const float* abias  = (const float*)d_in[5];
    const float* sn_g   = (const float*)d_in[6];
    const float* sn_b   = (const float*)d_in[7];
    const float* W_ih   = (const float*)d_in[8];
    const float* W_hh   = (const float*)d_in[9];
    const float* b_ih   = (const float*)d_in[10];
    const float* b_hh   = (const float*)d_in[11];
    const float* tn_g   = (const float*)d_in[12];
    const float* tn_b   = (const float*)d_in[13];
    float* out = (float*)d_out;

    gat_kernel<<<ROWS / 16, 128>>>(x, gat_W, gat_b);
    attn_kernel<<<(Bb * Tt) / 8, 256>>>(a_src, a_dst, abias, sn_g, sn_b);
    gx_kernel<<<dim3(ROWS / 32, 3), 256>>>(W_ih, b_ih);
    gru_tln_kernel<<<148, 384>>>(W_hh, b_hh, tn_g, tn_b, out);
}

// round 15
// speedup vs baseline: 1.2863x; 1.1672x over previous
#include <cuda_runtime.h>
#include <stdint.h>
#include <math.h>

#define Bb 64
#define Nn 3
#define Tt 4096
#define Dd 64
#define Hh 128
#define ROWS ((size_t)Bb * Nn * Tt)   // 786432

typedef unsigned long long u64;

// -------- packed f32x2 helpers (Blackwell fma.rn.f32x2) --------
__device__ __forceinline__ u64 pk(float lo, float hi) {
    u64 r; asm("mov.b64 %0,{%1,%2};" : "=l"(r) : "f"(lo), "f"(hi)); return r;
}
__device__ __forceinline__ void upk(u64 v, float& lo, float& hi) {
    asm("mov.b64 {%0,%1},%2;" : "=f"(lo), "=f"(hi) : "l"(v));
}
__device__ __forceinline__ u64 f2fma(u64 a, u64 b, u64 c) {
    u64 d; asm("fma.rn.f32x2 %0,%1,%2,%3;" : "=l"(d) : "l"(a), "l"(b), "l"(c)); return d;
}
__device__ __forceinline__ float fex2(float x) {
    float r; asm("ex2.approx.f32 %0,%1;" : "=f"(r) : "f"(x)); return r;
}
__device__ __forceinline__ float frcp(float x) {
    float r; asm("rcp.approx.f32 %0,%1;" : "=f"(r) : "f"(x)); return r;
}
#define LOG2E 1.4426950408889634f
__device__ __forceinline__ float fsig(float x) { return frcp(1.f + fex2(-x * LOG2E)); }
__device__ __forceinline__ float ftanh_f(float x) { return 1.f - 2.f * frcp(1.f + fex2(x * (2.f * LOG2E))); }

// -------- scratch (static device globals; no runtime allocation) --------
__device__ float g_h  [(size_t)Bb * Nn * Tt * Hh];
__device__ float g_hsp[(size_t)Bb * Nn * Tt * Hh];
__device__ float g_gx [(size_t)Bb * Nn * Tt * 3 * Hh];

// ============================================================
// Kernel A: h = x @ gat_W + gat_b      (786432 x 64) @ (64 x 128)  [f32x2]
// (proven, R2+)
// ============================================================
__global__ __launch_bounds__(128) void gat_kernel(const float* __restrict__ x,
                                                  const float* __restrict__ W,
                                                  const float* __restrict__ bias)
{
    __shared__ __align__(16) float xs[16][64];
    const int c = threadIdx.x;
    const size_t r0 = (size_t)blockIdx.x * 16;

    {
        const float4* src = (const float4*)(x + r0 * Dd);
        float4* dst = (float4*)xs;
        dst[c]       = src[c];
        dst[c + 128] = src[c + 128];
    }
    u64 w2[32];
#pragma unroll
    for (int i = 0; i < 32; i++)
        w2[i] = pk(W[(2 * i) * Hh + c], W[(2 * i + 1) * Hh + c]);
    const float bv = bias[c];
    __syncthreads();

#pragma unroll 4
    for (int r = 0; r < 16; r++) {
        const ulonglong2* xr = (const ulonglong2*)xs[r];
        u64 a0 = 0ull, a1 = 0ull;
#pragma unroll
        for (int i = 0; i < 16; i++) {
            ulonglong2 xv = xr[i];
            a0 = f2fma(xv.x, w2[2 * i],     a0);
            a1 = f2fma(xv.y, w2[2 * i + 1], a1);
        }
        float l0, h0, l1, h1; upk(a0, l0, h0); upk(a1, l1, h1);
        g_h[(r0 + r) * Hh + c] = (l0 + h0) + (l1 + h1) + bv;
    }
}

// ============================================================
// Kernel B: attention + softmax + ELU + spatial LayerNorm
// Warp-per-timestep (proven fastest, R9)
// ============================================================
__global__ __launch_bounds__(256) void attn_kernel(const float* __restrict__ a_src,
                                                   const float* __restrict__ a_dst,
                                                   const float* __restrict__ abias,
                                                   const float* __restrict__ sng,
                                                   const float* __restrict__ snb)
{
    const int lane = threadIdx.x & 31;
    const int wix  = blockIdx.x * 8 + (threadIdx.x >> 5);
    const int b = wix >> 12;
    const int t = wix & 4095;

    const float4 as4 = ((const float4*)a_src)[lane];
    const float4 ad4 = ((const float4*)a_dst)[lane];
    const float4 gw4 = ((const float4*)sng)[lane];
    const float4 gb4 = ((const float4*)snb)[lane];

    float bi[9];
#pragma unroll
    for (int q = 0; q < 9; q++) bi[q] = __ldg(abias + q);

    float4 hv[3];
#pragma unroll
    for (int j = 0; j < 3; j++)
        hv[j] = *(const float4*)(g_h + (((size_t)b * Nn + j) * Tt + t) * Hh + lane * 4);

    float v[6];
#pragma unroll
    for (int j = 0; j < 3; j++) {
        v[j]     = hv[j].x * as4.x + hv[j].y * as4.y + hv[j].z * as4.z + hv[j].w * as4.w;
        v[3 + j] = hv[j].x * ad4.x + hv[j].y * ad4.y + hv[j].z * ad4.z + hv[j].w * ad4.w;
    }
#pragma unroll
    for (int off = 16; off; off >>= 1) {
#pragma unroll
        for (int q = 0; q < 6; q++)
            v[q] += __shfl_xor_sync(0xffffffffu, v[q], off);
    }

    float4 o[3];
#pragma unroll
    for (int i = 0; i < 3; i++) {
        float sc[3];
#pragma unroll
        for (int j = 0; j < 3; j++) {
            float s = v[i] + v[3 + j];
            s = s > 0.f ? s : 0.2f * s;
            sc[j] = s + bi[i * 3 + j];
        }
        float mx = fmaxf(sc[0], fmaxf(sc[1], sc[2]));
        float e0 = __expf(sc[0] - mx), e1 = __expf(sc[1] - mx), e2 = __expf(sc[2] - mx);
        float inv = frcp(e0 + e1 + e2);
        e0 *= inv; e1 *= inv; e2 *= inv;
        float4 ov;
        ov.x = e0 * hv[0].x + e1 * hv[1].x + e2 * hv[2].x;
        ov.y = e0 * hv[0].y + e1 * hv[1].y + e2 * hv[2].y;
        ov.z = e0 * hv[0].z + e1 * hv[1].z + e2 * hv[2].z;
        ov.w = e0 * hv[0].w + e1 * hv[1].w + e2 * hv[2].w;
        ov.x = ov.x > 0.f ? ov.x : (__expf(ov.x) - 1.f);
        ov.y = ov.y > 0.f ? ov.y : (__expf(ov.y) - 1.f);
        ov.z = ov.z > 0.f ? ov.z : (__expf(ov.z) - 1.f);
        ov.w = ov.w > 0.f ? ov.w : (__expf(ov.w) - 1.f);
        o[i] = ov;
    }

    float st[6];
#pragma unroll
    for (int i = 0; i < 3; i++) {
        st[2*i]   = o[i].x + o[i].y + o[i].z + o[i].w;
        st[2*i+1] = o[i].x*o[i].x + o[i].y*o[i].y + o[i].z*o[i].z + o[i].w*o[i].w;
    }
#pragma unroll
    for (int off = 16; off; off >>= 1) {
#pragma unroll
        for (int q = 0; q < 6; q++)
            st[q] += __shfl_xor_sync(0xffffffffu, st[q], off);
    }
#pragma unroll
    for (int i = 0; i < 3; i++) {
        float mean = st[2*i] * (1.f / Hh);
        float var  = st[2*i+1] * (1.f / Hh) - mean * mean;
        float rstd = rsqrtf(var + 1e-5f);
        float4 r;
        r.x = (o[i].x - mean) * rstd * gw4.x + gb4.x;
        r.y = (o[i].y - mean) * rstd * gw4.y + gb4.y;
        r.z = (o[i].z - mean) * rstd * gw4.z + gb4.z;
        r.w = (o[i].w - mean) * rstd * gw4.w + gb4.w;
        *(float4*)(g_hsp + (((size_t)b * Nn + i) * Tt + t) * Hh + lane * 4) = r;
    }
}

// ============================================================
// Kernel C: gx = h_sp @ W_ih^T + b_ih   [f32x2]  (proven, R2+)
// ============================================================
__global__ __launch_bounds__(256) void gx_kernel(const float* __restrict__ Wih,
                                                 const float* __restrict__ bih)
{
    __shared__ __align__(16) float hs[32][128];
    __shared__ float ws[128][33];

    const int tid = threadIdx.x;
    const int gg  = tid & 127;
    const int rh  = tid >> 7;
    const int g0  = blockIdx.y * 128;
    const size_t r0 = (size_t)blockIdx.x * 32;

    {
        const float4* src = (const float4*)(g_hsp + r0 * Hh);
        float4* dst = (float4*)hs;
#pragma unroll
        for (int i = 0; i < 4; i++) dst[tid + 256 * i] = src[tid + 256 * i];
    }

    u64 acc[16];
#pragma unroll
    for (int i = 0; i < 16; i++) acc[i] = 0ull;

    for (int p = 0; p < 4; p++) {
        if (p) __syncthreads();
#pragma unroll
        for (int i = 0; i < 16; i++) {
            int idx = tid + 256 * i;
            int row = idx >> 5, k = idx & 31;
            ws[row][k] = Wih[(size_t)(g0 + row) * Hh + p * 32 + k];
        }
        __syncthreads();

        u64 w2[16];
#pragma unroll
        for (int i = 0; i < 16; i++)
            w2[i] = pk(ws[gg][2 * i], ws[gg][2 * i + 1]);

#pragma unroll
        for (int r = 0; r < 16; r++) {
            const ulonglong2* xr = (const ulonglong2*)(hs[rh * 16 + r] + p * 32);
#pragma unroll
            for (int i = 0; i < 8; i++) {
                ulonglong2 xv = xr[i];
                acc[r] = f2fma(xv.x, w2[2 * i],     acc[r]);
                acc[r] = f2fma(xv.y, w2[2 * i + 1], acc[r]);
            }
        }
    }

    const float bv = bih[g0 + gg];
#pragma unroll
    for (int r = 0; r < 16; r++) {
        size_t row = r0 + rh * 16 + r;
        float lo, hi; upk(acc[r], lo, hi);
        g_gx[row * 384 + g0 + gg] = lo + hi + bv;
    }
}

// ============================================================
// Kernel D: GRU — exact R5 core (best measured: 3.96 ms).
// 96 blocks x 384 threads; 2 seqs/block; K-split weights in regs;
// gate threads prefetch own gx one step ahead.
// ============================================================
__global__ __launch_bounds__(384, 1) void gru_kernel(const float* __restrict__ Whh,
                                                     const float* __restrict__ bhh,
                                                     float* __restrict__ out)
{
    const int u = threadIdx.x;                  // 0..383
    const int sA = blockIdx.x * 2;

    const int half  = (u >= 192) ? 1 : 0;
    const int rbase = u - half * 192;           // 0..191
    const int r1 = rbase, r2 = rbase + 192;

    __shared__ __align__(16) float hbuf[2][128];
    __shared__ u64 px[2][384];                  // [half][row] -> (partA, partB)

    u64 w1[32], w2r[32];
    {
        const u64* p1 = (const u64*)(Whh + (size_t)r1 * Hh + half * 64);
        const u64* p2 = (const u64*)(Whh + (size_t)r2 * Hh + half * 64);
#pragma unroll
        for (int i = 0; i < 32; i++) { w1[i] = p1[i]; w2r[i] = p2[i]; }
    }
    const float bh1 = half ? 0.f : bhh[r1];
    const float bh2 = half ? 0.f : bhh[r2];

    const int gq = u & 127;
    const int gs = (u >> 7) & 1;

    if (u < 128) { hbuf[0][u] = 0.f; hbuf[1][u] = 0.f; }

    const float* gxp = g_gx + (size_t)(sA + gs) * Tt * 384;
    float* op = out + (size_t)(sA + gs) * Tt * Hh;
    const float* pxf = (const float*)px;

    float fr = 0.f, fz = 0.f, fn = 0.f;
    if (u < 256) {
        fr = __ldg(gxp + gq);
        fz = __ldg(gxp + gq + 128);
        fn = __ldg(gxp + gq + 256);
    }
    __syncthreads();

    for (int t = 0; t < Tt; t++) {
        const ulonglong2* hA2 = (const ulonglong2*)(hbuf[0] + half * 64);
        const ulonglong2* hB2 = (const ulonglong2*)(hbuf[1] + half * 64);
        u64 a1A = 0ull, a2A = 0ull, a1B = 0ull, a2B = 0ull;
#pragma unroll
        for (int i = 0; i < 16; i++) {
            ulonglong2 ha = hA2[i];
            ulonglong2 hb = hB2[i];
            a1A = f2fma(w1[2*i],    ha.x, a1A);
            a2A = f2fma(w2r[2*i],   ha.x, a2A);
            a1B = f2fma(w1[2*i],    hb.x, a1B);
            a2B = f2fma(w2r[2*i],   hb.x, a2B);
            a1A = f2fma(w1[2*i+1],  ha.y, a1A);
            a2A = f2fma(w2r[2*i+1], ha.y, a2A);
            a1B = f2fma(w1[2*i+1],  hb.y, a1B);
            a2B = f2fma(w2r[2*i+1], hb.y, a2B);
        }
        float lo, hi;
        upk(a1A, lo, hi); const float p1A = lo + hi + bh1;
        upk(a2A, lo, hi); const float p2A = lo + hi + bh2;
        upk(a1B, lo, hi); const float p1B = lo + hi + bh1;
        upk(a2B, lo, hi); const float p2B = lo + hi + bh2;
        px[half][r1] = pk(p1A, p1B);
        px[half][r2] = pk(p2A, p2B);
        __syncthreads();

        if (u < 256) {
            const float ghr = pxf[(gq       ) * 2 + gs] + pxf[(384 + gq       ) * 2 + gs];
            const float ghz = pxf[(gq + 128 ) * 2 + gs] + pxf[(384 + gq + 128 ) * 2 + gs];
            const float ghn = pxf[(gq + 256 ) * 2 + gs] + pxf[(384 + gq + 256 ) * 2 + gs];
            const float r = fsig(fr + ghr);
            const float z = fsig(fz + ghz);
            const float n = ftanh_f(fn + r * ghn);
            const float hp = hbuf[gs][gq];
            const float hnew = (1.f - z) * n + z * hp;
            hbuf[gs][gq] = hnew;
            op[(size_t)t * Hh + gq] = hnew;

            const float* nx = gxp + (size_t)((t + 1 < Tt) ? t + 1 : t) * 384;
            fr = __ldg(nx + gq);
            fz = __ldg(nx + gq + 128);
            fn = __ldg(nx + gq + 256);
        }
        __syncthreads();
    }
}

// ============================================================
// Kernel E: temporal LayerNorm, in-place. One warp per row. (proven)
// ============================================================
__global__ __launch_bounds__(256) void tln_kernel(float* __restrict__ out,
                                                  const float* __restrict__ g,
                                                  const float* __restrict__ b)
{
    const int warp = threadIdx.x >> 5, lane = threadIdx.x & 31;
    const size_t row = (size_t)blockIdx.x * 8 + warp;
    float4* p = (float4*)(out + row * Hh);
    float4 v = p[lane];
    float s = v.x + v.y + v.z + v.w;
    float q = v.x * v.x + v.y * v.y + v.z * v.z + v.w * v.w;
#pragma unroll
    for (int off = 16; off; off >>= 1) {
        s += __shfl_xor_sync(0xffffffffu, s, off);
        q += __shfl_xor_sync(0xffffffffu, q, off);
    }
    const float mean = s * (1.f / Hh);
    const float var  = q * (1.f / Hh) - mean * mean;
    const float rstd = rsqrtf(var + 1e-5f);
    const float4 gv = ((const float4*)g)[lane];
    const float4 bv = ((const float4*)b)[lane];
    v.x = (v.x - mean) * rstd * gv.x + bv.x;
    v.y = (v.y - mean) * rstd * gv.y + bv.y;
    v.z = (v.z - mean) * rstd * gv.z + bv.z;
    v.w = (v.w - mean) * rstd * gv.w + bv.w;
    p[lane] = v;
}

// ============================================================
extern "C" void kernel_launch(void* const* d_in, const int* in_sizes, int n_in,
                              void* d_out, int out_size)
{
    const float* x      = (const float*)d_in[0];
    const float* gat_W  = (const float*)d_in[1];
    const float* gat_b  = (const float*)d_in[2];
    const float* a_src  = (const float*)d_in[3];
    const float* a_dst  = (const float*)d_in[4];
    const float* abias  = (const float*)d_in[5];
    const float* sn_g   = (const float*)d_in[6];
    const float* sn_b   = (const float*)d_in[7];
    const float* W_ih   = (const float*)d_in[8];
    const float* W_hh   = (const float*)d_in[9];
    const float* b_ih   = (const float*)d_in[10];
    const float* b_hh   = (const float*)d_in[11];
    const float* tn_g   = (const float*)d_in[12];
    const float* tn_b   = (const float*)d_in[13];
    float* out = (float*)d_out;

    gat_kernel<<<ROWS / 16, 128>>>(x, gat_W, gat_b);
    attn_kernel<<<(Bb * Tt) / 8, 256>>>(a_src, a_dst, abias, sn_g, sn_b);
    gx_kernel<<<dim3(ROWS / 32, 3), 256>>>(W_ih, b_ih);
    gru_kernel<<<Bb * Nn / 2, 384>>>(W_hh, b_hh, out);
    tln_kernel<<<ROWS / 8, 256>>>(out, tn_g, tn_b);
}

// round 16
// speedup vs baseline: 1.2875x; 1.0010x over previous
#include <cuda_runtime.h>
#include <stdint.h>
#include <math.h>

#define Bb 64
#define Nn 3
#define Tt 4096
#define Dd 64
#define Hh 128
#define ROWS ((size_t)Bb * Nn * Tt)   // 786432

typedef unsigned long long u64;

// -------- packed f32x2 helpers (Blackwell fma.rn.f32x2) --------
__device__ __forceinline__ u64 pk(float lo, float hi) {
    u64 r; asm("mov.b64 %0,{%1,%2};" : "=l"(r) : "f"(lo), "f"(hi)); return r;
}
__device__ __forceinline__ void upk(u64 v, float& lo, float& hi) {
    asm("mov.b64 {%0,%1},%2;" : "=f"(lo), "=f"(hi) : "l"(v));
}
__device__ __forceinline__ u64 f2fma(u64 a, u64 b, u64 c) {
    u64 d; asm("fma.rn.f32x2 %0,%1,%2,%3;" : "=l"(d) : "l"(a), "l"(b), "l"(c)); return d;
}
__device__ __forceinline__ float fex2(float x) {
    float r; asm("ex2.approx.f32 %0,%1;" : "=f"(r) : "f"(x)); return r;
}
__device__ __forceinline__ float frcp(float x) {
    float r; asm("rcp.approx.f32 %0,%1;" : "=f"(r) : "f"(x)); return r;
}
#define LOG2E 1.4426950408889634f
__device__ __forceinline__ float fsig(float x) { return frcp(1.f + fex2(-x * LOG2E)); }
__device__ __forceinline__ float ftanh_f(float x) { return 1.f - 2.f * frcp(1.f + fex2(x * (2.f * LOG2E))); }

// -------- scratch (static device globals; no runtime allocation) --------
__device__ float g_xm [(size_t)Bb * Nn * Tt * Dd];        // alpha-mixed x (B,N,T,64)
__device__ float g_hsp[(size_t)Bb * Nn * Tt * Hh];
__device__ float g_gx [(size_t)Bb * Nn * Tt * 3 * Hh];
__device__ float g_was[64], g_wad[64], g_bsd[2];          // W@a_src, W@a_dst, b.a_src, b.a_dst

// ============================================================
// Kernel P: precompute W@a_src, W@a_dst (64-vecs) and gat_b dots.
// ============================================================
__global__ void prep_attn(const float* __restrict__ W, const float* __restrict__ gb,
                          const float* __restrict__ asrc, const float* __restrict__ adst)
{
    int d = threadIdx.x;
    if (d < 64) {
        float s = 0.f, t = 0.f;
        for (int h = 0; h < Hh; h++) {
            float w = W[d * Hh + h];
            s += w * asrc[h];
            t += w * adst[h];
        }
        g_was[d] = s; g_wad[d] = t;
    } else if (d == 64 || d == 65) {
        const float* a = (d == 64) ? asrc : adst;
        float s = 0.f;
        for (int h = 0; h < Hh; h++) s += gb[h] * a[h];
        g_bsd[d - 64] = s;
    }
}

// ============================================================
// Kernel M: scores + softmax + alpha-mix in D=64 space (mem-bound).
// Warp per (b,t); lane holds 2 x-columns per node.
//   s_src[j] = x_j . was + bs ;  s_dst[j] = x_j . wad + bd
//   xmix[i]  = sum_j alpha[i][j] * x_j
// ============================================================
__global__ __launch_bounds__(256) void mix_kernel(const float* __restrict__ x,
                                                  const float* __restrict__ abias)
{
    const int lane = threadIdx.x & 31;
    const int wix  = blockIdx.x * 8 + (threadIdx.x >> 5);
    const int b = wix >> 12;
    const int t = wix & 4095;

    const float2 was = ((const float2*)g_was)[lane];
    const float2 wad = ((const float2*)g_wad)[lane];
    const float bs = g_bsd[0], bd = g_bsd[1];

    float bi[9];
#pragma unroll
    for (int q = 0; q < 9; q++) bi[q] = __ldg(abias + q);

    float2 xv[3];
#pragma unroll
    for (int j = 0; j < 3; j++)
        xv[j] = *(const float2*)(x + (((size_t)b * Nn + j) * Tt + t) * Dd + lane * 2);

    float v[6];
#pragma unroll
    for (int j = 0; j < 3; j++) {
        v[j]     = xv[j].x * was.x + xv[j].y * was.y;
        v[3 + j] = xv[j].x * wad.x + xv[j].y * wad.y;
    }
#pragma unroll
    for (int off = 16; off; off >>= 1) {
#pragma unroll
        for (int q = 0; q < 6; q++)
            v[q] += __shfl_xor_sync(0xffffffffu, v[q], off);
    }
    float ss[3], sd[3];
#pragma unroll
    for (int j = 0; j < 3; j++) { ss[j] = v[j] + bs; sd[j] = v[3 + j] + bd; }

#pragma unroll
    for (int i = 0; i < 3; i++) {
        float sc[3];
#pragma unroll
        for (int j = 0; j < 3; j++) {
            float s = ss[i] + sd[j];
            s = s > 0.f ? s : 0.2f * s;          // leaky_relu(0.2)
            sc[j] = s + bi[i * 3 + j];
        }
        float mx = fmaxf(sc[0], fmaxf(sc[1], sc[2]));
        float e0 = __expf(sc[0] - mx), e1 = __expf(sc[1] - mx), e2 = __expf(sc[2] - mx);
        float inv = frcp(e0 + e1 + e2);
        e0 *= inv; e1 *= inv; e2 *= inv;
        float2 m;
        m.x = e0 * xv[0].x + e1 * xv[1].x + e2 * xv[2].x;
        m.y = e0 * xv[0].y + e1 * xv[1].y + e2 * xv[2].y;
        *(float2*)(g_xm + (((size_t)b * Nn + i) * Tt + t) * Dd + lane * 2) = m;
    }
}

// ============================================================
// Kernel G: h_sp = LN(elu(xmix @ W + gat_b))   [f32x2 GEMM + fused epilogue]
// 16 rows/block, 128 threads (thread = H column, W column in 32 u64 regs).
// ============================================================
__global__ __launch_bounds__(128) void gemm_eln_kernel(const float* __restrict__ W,
                                                       const float* __restrict__ bias,
                                                       const float* __restrict__ sng,
                                                       const float* __restrict__ snb)
{
    __shared__ __align__(16) float xs[16][64];
    __shared__ float vs[16][128];
    __shared__ float mr[16][2];

    const int c = threadIdx.x;
    const int warp = c >> 5, lane = c & 31;
    const size_t r0 = (size_t)blockIdx.x * 16;

    {
        const float4* src = (const float4*)(g_xm + r0 * Dd);
        float4* dst = (float4*)xs;
        dst[c]       = src[c];
        dst[c + 128] = src[c + 128];
    }
    u64 w2[32];
#pragma unroll
    for (int i = 0; i < 32; i++)
        w2[i] = pk(W[(2 * i) * Hh + c], W[(2 * i + 1) * Hh + c]);
    const float bv = bias[c];
    const float gw = sng[c], gb = snb[c];
    __syncthreads();

    float v[16];
#pragma unroll 4
    for (int r = 0; r < 16; r++) {
        const ulonglong2* xr = (const ulonglong2*)xs[r];
        u64 a0 = 0ull, a1 = 0ull;
#pragma unroll
        for (int i = 0; i < 16; i++) {
            ulonglong2 xw = xr[i];
            a0 = f2fma(xw.x, w2[2 * i],     a0);
            a1 = f2fma(xw.y, w2[2 * i + 1], a1);
        }
        float l0, h0, l1, h1; upk(a0, l0, h0); upk(a1, l1, h1);
        float val = (l0 + h0) + (l1 + h1) + bv;
        val = val > 0.f ? val : (__expf(val) - 1.f);   // ELU
        v[r] = val;
        vs[r][c] = val;
    }
    __syncthreads();

    // spatial LN stats: warp w reduces rows 4w..4w+3
#pragma unroll
    for (int k = 0; k < 4; k++) {
        const int r = warp * 4 + k;
        float a0 = vs[r][lane], a1 = vs[r][lane + 32], a2 = vs[r][lane + 64], a3 = vs[r][lane + 96];
        float s = (a0 + a1) + (a2 + a3);
        float q = (a0 * a0 + a1 * a1) + (a2 * a2 + a3 * a3);
#pragma unroll
        for (int off = 16; off; off >>= 1) {
            s += __shfl_xor_sync(0xffffffffu, s, off);
            q += __shfl_xor_sync(0xffffffffu, q, off);
        }
        if (lane == 0) {
            float mean = s * (1.f / Hh);
            float var  = q * (1.f / Hh) - mean * mean;
            mr[r][0] = mean;
            mr[r][1] = rsqrtf(var + 1e-5f);
        }
    }
    __syncthreads();

#pragma unroll
    for (int r = 0; r < 16; r++)
        g_hsp[(r0 + r) * Hh + c] = (v[r] - mr[r][0]) * mr[r][1] * gw + gb;
}

// ============================================================
// Kernel C: gx = h_sp @ W_ih^T + b_ih   [f32x2]  (proven, R2+)
// ============================================================
__global__ __launch_bounds__(256) void gx_kernel(const float* __restrict__ Wih,
                                                 const float* __restrict__ bih)
{
    __shared__ __align__(16) float hs[32][128];
    __shared__ float ws[128][33];

    const int tid = threadIdx.x;
    const int gg  = tid & 127;
    const int rh  = tid >> 7;
    const int g0  = blockIdx.y * 128;
    const size_t r0 = (size_t)blockIdx.x * 32;

    {
        const float4* src = (const float4*)(g_hsp + r0 * Hh);
        float4* dst = (float4*)hs;
#pragma unroll
        for (int i = 0; i < 4; i++) dst[tid + 256 * i] = src[tid + 256 * i];
    }

    u64 acc[16];
#pragma unroll
    for (int i = 0; i < 16; i++) acc[i] = 0ull;

    for (int p = 0; p < 4; p++) {
        if (p) __syncthreads();
#pragma unroll
        for (int i = 0; i < 16; i++) {
            int idx = tid + 256 * i;
            int row = idx >> 5, k = idx & 31;
            ws[row][k] = Wih[(size_t)(g0 + row) * Hh + p * 32 + k];
        }
        __syncthreads();

        u64 w2[16];
#pragma unroll
        for (int i = 0; i < 16; i++)
            w2[i] = pk(ws[gg][2 * i], ws[gg][2 * i + 1]);

#pragma unroll
        for (int r = 0; r < 16; r++) {
            const ulonglong2* xr = (const ulonglong2*)(hs[rh * 16 + r] + p * 32);
#pragma unroll
            for (int i = 0; i < 8; i++) {
                ulonglong2 xv = xr[i];
                acc[r] = f2fma(xv.x, w2[2 * i],     acc[r]);
                acc[r] = f2fma(xv.y, w2[2 * i + 1], acc[r]);
            }
        }
    }

    const float bv = bih[g0 + gg];
#pragma unroll
    for (int r = 0; r < 16; r++) {
        size_t row = r0 + rh * 16 + r;
        float lo, hi; upk(acc[r], lo, hi);
        g_gx[row * 384 + g0 + gg] = lo + hi + bv;
    }
}

// ============================================================
// Kernel D: GRU — exact R5 core (best measured).
// ============================================================
__global__ __launch_bounds__(384, 1) void gru_kernel(const float* __restrict__ Whh,
                                                     const float* __restrict__ bhh,
                                                     float* __restrict__ out)
{
    const int u = threadIdx.x;                  // 0..383
    const int sA = blockIdx.x * 2;

    const int half  = (u >= 192) ? 1 : 0;
    const int rbase = u - half * 192;           // 0..191
    const int r1 = rbase, r2 = rbase + 192;

    __shared__ __align__(16) float hbuf[2][128];
    __shared__ u64 px[2][384];                  // [half][row] -> (partA, partB)

    u64 w1[32], w2r[32];
    {
        const u64* p1 = (const u64*)(Whh + (size_t)r1 * Hh + half * 64);
        const u64* p2 = (const u64*)(Whh + (size_t)r2 * Hh + half * 64);
#pragma unroll
        for (int i = 0; i < 32; i++) { w1[i] = p1[i]; w2r[i] = p2[i]; }
    }
    const float bh1 = half ? 0.f : bhh[r1];
    const float bh2 = half ? 0.f : bhh[r2];

    const int gq = u & 127;
    const int gs = (u >> 7) & 1;

    if (u < 128) { hbuf[0][u] = 0.f; hbuf[1][u] = 0.f; }

    const float* gxp = g_gx + (size_t)(sA + gs) * Tt * 384;
    float* op = out + (size_t)(sA + gs) * Tt * Hh;
    const float* pxf = (const float*)px;

    float fr = 0.f, fz = 0.f, fn = 0.f;
    if (u < 256) {
        fr = __ldg(gxp + gq);
        fz = __ldg(gxp + gq + 128);
        fn = __ldg(gxp + gq + 256);
    }
    __syncthreads();

    for (int t = 0; t < Tt; t++) {
        const ulonglong2* hA2 = (const ulonglong2*)(hbuf[0] + half * 64);
        const ulonglong2* hB2 = (const ulonglong2*)(hbuf[1] + half * 64);
        u64 a1A = 0ull, a2A = 0ull, a1B = 0ull, a2B = 0ull;
#pragma unroll
        for (int i = 0; i < 16; i++) {
            ulonglong2 ha = hA2[i];
            ulonglong2 hb = hB2[i];
            a1A = f2fma(w1[2*i],    ha.x, a1A);
            a2A = f2fma(w2r[2*i],   ha.x, a2A);
            a1B = f2fma(w1[2*i],    hb.x, a1B);
            a2B = f2fma(w2r[2*i],   hb.x, a2B);
            a1A = f2fma(w1[2*i+1],  ha.y, a1A);
            a2A = f2fma(w2r[2*i+1], ha.y, a2A);
            a1B = f2fma(w1[2*i+1],  hb.y, a1B);
            a2B = f2fma(w2r[2*i+1], hb.y, a2B);
        }
        float lo, hi;
        upk(a1A, lo, hi); const float p1A = lo + hi + bh1;
        upk(a2A, lo, hi); const float p2A = lo + hi + bh2;
        upk(a1B, lo, hi); const float p1B = lo + hi + bh1;
        upk(a2B, lo, hi); const float p2B = lo + hi + bh2;
        px[half][r1] = pk(p1A, p1B);
        px[half][r2] = pk(p2A, p2B);
        __syncthreads();

        if (u < 256) {
            const float ghr = pxf[(gq       ) * 2 + gs] + pxf[(384 + gq       ) * 2 + gs];
            const float ghz = pxf[(gq + 128 ) * 2 + gs] + pxf[(384 + gq + 128 ) * 2 + gs];
            const float ghn = pxf[(gq + 256 ) * 2 + gs] + pxf[(384 + gq + 256 ) * 2 + gs];
            const float r = fsig(fr + ghr);
            const float z = fsig(fz + ghz);
            const float n = ftanh_f(fn + r * ghn);
            const float hp = hbuf[gs][gq];
            const float hnew = (1.f - z) * n + z * hp;
            hbuf[gs][gq] = hnew;
            op[(size_t)t * Hh + gq] = hnew;

            const float* nx = gxp + (size_t)((t + 1 < Tt) ? t + 1 : t) * 384;
            fr = __ldg(nx + gq);
            fz = __ldg(nx + gq + 128);
            fn = __ldg(nx + gq + 256);
        }
        __syncthreads();
    }
}

// ============================================================
// Kernel E: temporal LayerNorm, in-place. One warp per row. (proven)
// ============================================================
__global__ __launch_bounds__(256) void tln_kernel(float* __restrict__ out,
                                                  const float* __restrict__ g,
                                                  const float* __restrict__ b)
{
    const int warp = threadIdx.x >> 5, lane = threadIdx.x & 31;
    const size_t row = (size_t)blockIdx.x * 8 + warp;
    float4* p = (float4*)(out + row * Hh);
    float4 v = p[lane];
    float s = v.x + v.y + v.z + v.w;
    float q = v.x * v.x + v.y * v.y + v.z * v.z + v.w * v.w;
#pragma unroll
    for (int off = 16; off; off >>= 1) {
        s += __shfl_xor_sync(0xffffffffu, s, off);
        q += __shfl_xor_sync(0xffffffffu, q, off);
    }
    const float mean = s * (1.f / Hh);
    const float var  = q * (1.f / Hh) - mean * mean;
    const float rstd = rsqrtf(var + 1e-5f);
    const float4 gv = ((const float4*)g)[lane];
    const float4 bv = ((const float4*)b)[lane];
    v.x = (v.x - mean) * rstd * gv.x + bv.x;
    v.y = (v.y - mean) * rstd * gv.y + bv.y;
    v.z = (v.z - mean) * rstd * gv.z + bv.z;
    v.w = (v.w - mean) * rstd * gv.w + bv.w;
    p[lane] = v;
}

// ============================================================
extern "C" void kernel_launch(void* const* d_in, const int* in_sizes, int n_in,
                              void* d_out, int out_size)
{
    const float* x      = (const float*)d_in[0];
    const float* gat_W  = (const float*)d_in[1];
    const float* gat_b  = (const float*)d_in[2];
    const float* a_src  = (const float*)d_in[3];
    const float* a_dst  = (const float*)d_in[4];
    const float* abias  = (const float*)d_in[5];
    const float* sn_g   = (const float*)d_in[6];
    const float* sn_b   = (const float*)d_in[7];
    const float* W_ih   = (const float*)d_in[8];
    const float* W_hh   = (const float*)d_in[9];
    const float* b_ih   = (const float*)d_in[10];
    const float* b_hh   = (const float*)d_in[11];
    const float* tn_g   = (const float*)d_in[12];
    const float* tn_b   = (const float*)d_in[13];
    float* out = (float*)d_out;

    prep_attn<<<1, 128>>>(gat_W, gat_b, a_src, a_dst);
    mix_kernel<<<(Bb * Tt) / 8, 256>>>(x, abias);
    gemm_eln_kernel<<<ROWS / 16, 128>>>(gat_W, gat_b, sn_g, sn_b);
    gx_kernel<<<dim3(ROWS / 32, 3), 256>>>(W_ih, b_ih);
    gru_kernel<<<Bb * Nn / 2, 384>>>(W_hh, b_hh, out);
    tln_kernel<<<ROWS / 8, 256>>>(out, tn_g, tn_b);
}

// round 17
// speedup vs baseline: 1.4221x; 1.1045x over previous
#include <cuda_runtime.h>
#include <stdint.h>
#include <math.h>

#define Bb 64
#define Nn 3
#define Tt 4096
#define Dd 64
#define Hh 128
#define ROWS ((size_t)Bb * Nn * Tt)   // 786432

typedef unsigned long long u64;

// -------- packed f32x2 helpers (Blackwell fma.rn.f32x2) --------
__device__ __forceinline__ u64 pk(float lo, float hi) {
    u64 r; asm("mov.b64 %0,{%1,%2};" : "=l"(r) : "f"(lo), "f"(hi)); return r;
}
__device__ __forceinline__ void upk(u64 v, float& lo, float& hi) {
    asm("mov.b64 {%0,%1},%2;" : "=f"(lo), "=f"(hi) : "l"(v));
}
__device__ __forceinline__ u64 f2fma(u64 a, u64 b, u64 c) {
    u64 d; asm("fma.rn.f32x2 %0,%1,%2,%3;" : "=l"(d) : "l"(a), "l"(b), "l"(c)); return d;
}
__device__ __forceinline__ float fex2(float x) {
    float r; asm("ex2.approx.f32 %0,%1;" : "=f"(r) : "f"(x)); return r;
}
__device__ __forceinline__ float frcp(float x) {
    float r; asm("rcp.approx.f32 %0,%1;" : "=f"(r) : "f"(x)); return r;
}
#define LOG2E 1.4426950408889634f
__device__ __forceinline__ float fsig(float x) { return frcp(1.f + fex2(-x * LOG2E)); }
__device__ __forceinline__ float ftanh_f(float x) { return 1.f - 2.f * frcp(1.f + fex2(x * (2.f * LOG2E))); }

// -------- scratch (static device globals; no runtime allocation) --------
__device__ float g_xm [(size_t)Bb * Nn * Tt * Dd];        // alpha-mixed x (B,N,T,64)
__device__ float g_hsp[(size_t)Bb * Nn * Tt * Hh];
__device__ float g_gx [(size_t)Bb * Nn * Tt * 3 * Hh];
__device__ float g_was[64], g_wad[64], g_bsd[2];          // W@a_src, W@a_dst, b.a_src, b.a_dst

// ============================================================
// Kernel P: precompute W@a_src, W@a_dst (64-vecs) and gat_b dots.
// ============================================================
__global__ void prep_attn(const float* __restrict__ W, const float* __restrict__ gb,
                          const float* __restrict__ asrc, const float* __restrict__ adst)
{
    int d = threadIdx.x;
    if (d < 64) {
        float s = 0.f, t = 0.f;
        for (int h = 0; h < Hh; h++) {
            float w = W[d * Hh + h];
            s += w * asrc[h];
            t += w * adst[h];
        }
        g_was[d] = s; g_wad[d] = t;
    } else if (d == 64 || d == 65) {
        const float* a = (d == 64) ? asrc : adst;
        float s = 0.f;
        for (int h = 0; h < Hh; h++) s += gb[h] * a[h];
        g_bsd[d - 64] = s;
    }
}

// ============================================================
// Kernel M: scores + softmax + alpha-mix in D=64 space (proven R16)
// ============================================================
__global__ __launch_bounds__(256) void mix_kernel(const float* __restrict__ x,
                                                  const float* __restrict__ abias)
{
    const int lane = threadIdx.x & 31;
    const int wix  = blockIdx.x * 8 + (threadIdx.x >> 5);
    const int b = wix >> 12;
    const int t = wix & 4095;

    const float2 was = ((const float2*)g_was)[lane];
    const float2 wad = ((const float2*)g_wad)[lane];
    const float bs = g_bsd[0], bd = g_bsd[1];

    float bi[9];
#pragma unroll
    for (int q = 0; q < 9; q++) bi[q] = __ldg(abias + q);

    float2 xv[3];
#pragma unroll
    for (int j = 0; j < 3; j++)
        xv[j] = *(const float2*)(x + (((size_t)b * Nn + j) * Tt + t) * Dd + lane * 2);

    float v[6];
#pragma unroll
    for (int j = 0; j < 3; j++) {
        v[j]     = xv[j].x * was.x + xv[j].y * was.y;
        v[3 + j] = xv[j].x * wad.x + xv[j].y * wad.y;
    }
#pragma unroll
    for (int off = 16; off; off >>= 1) {
#pragma unroll
        for (int q = 0; q < 6; q++)
            v[q] += __shfl_xor_sync(0xffffffffu, v[q], off);
    }
    float ss[3], sd[3];
#pragma unroll
    for (int j = 0; j < 3; j++) { ss[j] = v[j] + bs; sd[j] = v[3 + j] + bd; }

#pragma unroll
    for (int i = 0; i < 3; i++) {
        float sc[3];
#pragma unroll
        for (int j = 0; j < 3; j++) {
            float s = ss[i] + sd[j];
            s = s > 0.f ? s : 0.2f * s;          // leaky_relu(0.2)
            sc[j] = s + bi[i * 3 + j];
        }
        float mx = fmaxf(sc[0], fmaxf(sc[1], sc[2]));
        float e0 = __expf(sc[0] - mx), e1 = __expf(sc[1] - mx), e2 = __expf(sc[2] - mx);
        float inv = frcp(e0 + e1 + e2);
        e0 *= inv; e1 *= inv; e2 *= inv;
        float2 m;
        m.x = e0 * xv[0].x + e1 * xv[1].x + e2 * xv[2].x;
        m.y = e0 * xv[0].y + e1 * xv[1].y + e2 * xv[2].y;
        *(float2*)(g_xm + (((size_t)b * Nn + i) * Tt + t) * Dd + lane * 2) = m;
    }
}

// ============================================================
// Kernel G: h_sp = LN(elu(xmix @ W + gat_b))  (proven R16)
// ============================================================
__global__ __launch_bounds__(128) void gemm_eln_kernel(const float* __restrict__ W,
                                                       const float* __restrict__ bias,
                                                       const float* __restrict__ sng,
                                                       const float* __restrict__ snb)
{
    __shared__ __align__(16) float xs[16][64];
    __shared__ float vs[16][128];
    __shared__ float mr[16][2];

    const int c = threadIdx.x;
    const int warp = c >> 5, lane = c & 31;
    const size_t r0 = (size_t)blockIdx.x * 16;

    {
        const float4* src = (const float4*)(g_xm + r0 * Dd);
        float4* dst = (float4*)xs;
        dst[c]       = src[c];
        dst[c + 128] = src[c + 128];
    }
    u64 w2[32];
#pragma unroll
    for (int i = 0; i < 32; i++)
        w2[i] = pk(W[(2 * i) * Hh + c], W[(2 * i + 1) * Hh + c]);
    const float bv = bias[c];
    const float gw = sng[c], gb = snb[c];
    __syncthreads();

    float v[16];
#pragma unroll 4
    for (int r = 0; r < 16; r++) {
        const ulonglong2* xr = (const ulonglong2*)xs[r];
        u64 a0 = 0ull, a1 = 0ull;
#pragma unroll
        for (int i = 0; i < 16; i++) {
            ulonglong2 xw = xr[i];
            a0 = f2fma(xw.x, w2[2 * i],     a0);
            a1 = f2fma(xw.y, w2[2 * i + 1], a1);
        }
        float l0, h0, l1, h1; upk(a0, l0, h0); upk(a1, l1, h1);
        float val = (l0 + h0) + (l1 + h1) + bv;
        val = val > 0.f ? val : (__expf(val) - 1.f);   // ELU
        v[r] = val;
        vs[r][c] = val;
    }
    __syncthreads();

#pragma unroll
    for (int k = 0; k < 4; k++) {
        const int r = warp * 4 + k;
        float a0 = vs[r][lane], a1 = vs[r][lane + 32], a2 = vs[r][lane + 64], a3 = vs[r][lane + 96];
        float s = (a0 + a1) + (a2 + a3);
        float q = (a0 * a0 + a1 * a1) + (a2 * a2 + a3 * a3);
#pragma unroll
        for (int off = 16; off; off >>= 1) {
            s += __shfl_xor_sync(0xffffffffu, s, off);
            q += __shfl_xor_sync(0xffffffffu, q, off);
        }
        if (lane == 0) {
            float mean = s * (1.f / Hh);
            float var  = q * (1.f / Hh) - mean * mean;
            mr[r][0] = mean;
            mr[r][1] = rsqrtf(var + 1e-5f);
        }
    }
    __syncthreads();

#pragma unroll
    for (int r = 0; r < 16; r++)
        g_hsp[(r0 + r) * Hh + c] = (v[r] - mr[r][0]) * mr[r][1] * gw + gb;
}

// ============================================================
// Kernel C: gx = h_sp @ W_ih^T + b_ih   [f32x2, 2 cols/thread]
// Thread: cols {g0+gg, g0+gg+64} x 8 rows -> each broadcast hs load
// feeds 2 columns (halves LDS wavefronts vs 1-col version).
// ws padded to 34 floats: 8B-aligned, conflict-free LDS.64.
// ============================================================
__global__ __launch_bounds__(256) void gx_kernel(const float* __restrict__ Wih,
                                                 const float* __restrict__ bih)
{
    __shared__ __align__(16) float hs[32][128];   // 16 KB
    __shared__ __align__(8)  float ws[128][34];   // 17.4 KB

    const int tid = threadIdx.x;
    const int gg  = tid & 63;           // column pair base
    const int rh  = tid >> 6;           // 0..3 -> rows rh*8..rh*8+7
    const int g0  = blockIdx.y * 128;
    const size_t r0 = (size_t)blockIdx.x * 32;

    {
        const float4* src = (const float4*)(g_hsp + r0 * Hh);
        float4* dst = (float4*)hs;
#pragma unroll
        for (int i = 0; i < 4; i++) dst[tid + 256 * i] = src[tid + 256 * i];
    }

    u64 accA[8], accB[8];
#pragma unroll
    for (int i = 0; i < 8; i++) { accA[i] = 0ull; accB[i] = 0ull; }

    for (int p = 0; p < 4; p++) {
        if (p) __syncthreads();
        // stage W_ih[g0..g0+128)[p*32..p*32+32) coalesced
#pragma unroll
        for (int i = 0; i < 16; i++) {
            int idx = tid + 256 * i;            // 0..4095
            int row = idx >> 5, k = idx & 31;
            ws[row][k] = Wih[(size_t)(g0 + row) * Hh + p * 32 + k];
        }
        __syncthreads();

#pragma unroll
        for (int h2 = 0; h2 < 2; h2++) {
            u64 wA[8], wB[8];
#pragma unroll
            for (int i = 0; i < 8; i++) {
                wA[i] = *(const u64*)&ws[gg     ][h2 * 16 + 2 * i];
                wB[i] = *(const u64*)&ws[gg + 64][h2 * 16 + 2 * i];
            }
#pragma unroll
            for (int r = 0; r < 8; r++) {
                const ulonglong2* xr = (const ulonglong2*)(hs[rh * 8 + r] + p * 32 + h2 * 16);
#pragma unroll
                for (int i = 0; i < 4; i++) {
                    ulonglong2 xv = xr[i];
                    accA[r] = f2fma(xv.x, wA[2 * i],     accA[r]);
                    accB[r] = f2fma(xv.x, wB[2 * i],     accB[r]);
                    accA[r] = f2fma(xv.y, wA[2 * i + 1], accA[r]);
                    accB[r] = f2fma(xv.y, wB[2 * i + 1], accB[r]);
                }
            }
        }
    }

    const float bvA = bih[g0 + gg];
    const float bvB = bih[g0 + gg + 64];
#pragma unroll
    for (int r = 0; r < 8; r++) {
        size_t row = r0 + rh * 8 + r;
        float lo, hi;
        upk(accA[r], lo, hi);
        g_gx[row * 384 + g0 + gg]      = lo + hi + bvA;
        upk(accB[r], lo, hi);
        g_gx[row * 384 + g0 + gg + 64] = lo + hi + bvB;
    }
}

// ============================================================
// Kernel D: GRU — exact R5 core (best measured).
// ============================================================
__global__ __launch_bounds__(384, 1) void gru_kernel(const float* __restrict__ Whh,
                                                     const float* __restrict__ bhh,
                                                     float* __restrict__ out)
{
    const int u = threadIdx.x;                  // 0..383
    const int sA = blockIdx.x * 2;

    const int half  = (u >= 192) ? 1 : 0;
    const int rbase = u - half * 192;           // 0..191
    const int r1 = rbase, r2 = rbase + 192;

    __shared__ __align__(16) float hbuf[2][128];
    __shared__ u64 px[2][384];                  // [half][row] -> (partA, partB)

    u64 w1[32], w2r[32];
    {
        const u64* p1 = (const u64*)(Whh + (size_t)r1 * Hh + half * 64);
        const u64* p2 = (const u64*)(Whh + (size_t)r2 * Hh + half * 64);
#pragma unroll
        for (int i = 0; i < 32; i++) { w1[i] = p1[i]; w2r[i] = p2[i]; }
    }
    const float bh1 = half ? 0.f : bhh[r1];
    const float bh2 = half ? 0.f : bhh[r2];

    const int gq = u & 127;
    const int gs = (u >> 7) & 1;

    if (u < 128) { hbuf[0][u] = 0.f; hbuf[1][u] = 0.f; }

    const float* gxp = g_gx + (size_t)(sA + gs) * Tt * 384;
    float* op = out + (size_t)(sA + gs) * Tt * Hh;
    const float* pxf = (const float*)px;

    float fr = 0.f, fz = 0.f, fn = 0.f;
    if (u < 256) {
        fr = __ldg(gxp + gq);
        fz = __ldg(gxp + gq + 128);
        fn = __ldg(gxp + gq + 256);
    }
    __syncthreads();

    for (int t = 0; t < Tt; t++) {
        const ulonglong2* hA2 = (const ulonglong2*)(hbuf[0] + half * 64);
        const ulonglong2* hB2 = (const ulonglong2*)(hbuf[1] + half * 64);
        u64 a1A = 0ull, a2A = 0ull, a1B = 0ull, a2B = 0ull;
#pragma unroll
        for (int i = 0; i < 16; i++) {
            ulonglong2 ha = hA2[i];
            ulonglong2 hb = hB2[i];
            a1A = f2fma(w1[2*i],    ha.x, a1A);
            a2A = f2fma(w2r[2*i],   ha.x, a2A);
            a1B = f2fma(w1[2*i],    hb.x, a1B);
            a2B = f2fma(w2r[2*i],   hb.x, a2B);
            a1A = f2fma(w1[2*i+1],  ha.y, a1A);
            a2A = f2fma(w2r[2*i+1], ha.y, a2A);
            a1B = f2fma(w1[2*i+1],  hb.y, a1B);
            a2B = f2fma(w2r[2*i+1], hb.y, a2B);
        }
        float lo, hi;
        upk(a1A, lo, hi); const float p1A = lo + hi + bh1;
        upk(a2A, lo, hi); const float p2A = lo + hi + bh2;
        upk(a1B, lo, hi); const float p1B = lo + hi + bh1;
        upk(a2B, lo, hi); const float p2B = lo + hi + bh2;
        px[half][r1] = pk(p1A, p1B);
        px[half][r2] = pk(p2A, p2B);
        __syncthreads();

        if (u < 256) {
            const float ghr = pxf[(gq       ) * 2 + gs] + pxf[(384 + gq       ) * 2 + gs];
            const float ghz = pxf[(gq + 128 ) * 2 + gs] + pxf[(384 + gq + 128 ) * 2 + gs];
            const float ghn = pxf[(gq + 256 ) * 2 + gs] + pxf[(384 + gq + 256 ) * 2 + gs];
            const float r = fsig(fr + ghr);
            const float z = fsig(fz + ghz);
            const float n = ftanh_f(fn + r * ghn);
            const float hp = hbuf[gs][gq];
            const float hnew = (1.f - z) * n + z * hp;
            hbuf[gs][gq] = hnew;
            op[(size_t)t * Hh + gq] = hnew;

            const float* nx = gxp + (size_t)((t + 1 < Tt) ? t + 1 : t) * 384;
            fr = __ldg(nx + gq);
            fz = __ldg(nx + gq + 128);
            fn = __ldg(nx + gq + 256);
        }
        __syncthreads();
    }
}

// ============================================================
// Kernel E: temporal LayerNorm, in-place. One warp per row. (proven)
// ============================================================
__global__ __launch_bounds__(256) void tln_kernel(float* __restrict__ out,
                                                  const float* __restrict__ g,
                                                  const float* __restrict__ b)
{
    const int warp = threadIdx.x >> 5, lane = threadIdx.x & 31;
    const size_t row = (size_t)blockIdx.x * 8 + warp;
    float4* p = (float4*)(out + row * Hh);
    float4 v = p[lane];
    float s = v.x + v.y + v.z + v.w;
    float q = v.x * v.x + v.y * v.y + v.z * v.z + v.w * v.w;
#pragma unroll
    for (int off = 16; off; off >>= 1) {
        s += __shfl_xor_sync(0xffffffffu, s, off);
        q += __shfl_xor_sync(0xffffffffu, q, off);
    }
    const float mean = s * (1.f / Hh);
    const float var  = q * (1.f / Hh) - mean * mean;
    const float rstd = rsqrtf(var + 1e-5f);
    const float4 gv = ((const float4*)g)[lane];
    const float4 bv = ((const float4*)b)[lane];
    v.x = (v.x - mean) * rstd * gv.x + bv.x;
    v.y = (v.y - mean) * rstd * gv.y + bv.y;
    v.z = (v.z - mean) * rstd * gv.z + bv.z;
    v.w = (v.w - mean) * rstd * gv.w + bv.w;
    p[lane] = v;
}

// ============================================================
extern "C" void kernel_launch(void* const* d_in, const int* in_sizes, int n_in,
                              void* d_out, int out_size)
{
    const float* x      = (const float*)d_in[0];
    const float* gat_W  = (const float*)d_in[1];
    const float* gat_b  = (const float*)d_in[2];
    const float* a_src  = (const float*)d_in[3];
    const float* a_dst  = (const float*)d_in[4];
    const float* abias  = (const float*)d_in[5];
    const float* sn_g   = (const float*)d_in[6];
    const float* sn_b   = (const float*)d_in[7];
    const float* W_ih   = (const float*)d_in[8];
    const float* W_hh   = (const float*)d_in[9];
    const float* b_ih   = (const float*)d_in[10];
    const float* b_hh   = (const float*)d_in[11];
    const float* tn_g   = (const float*)d_in[12];
    const float* tn_b   = (const float*)d_in[13];
    float* out = (float*)d_out;

    prep_attn<<<1, 128>>>(gat_W, gat_b, a_src, a_dst);
    mix_kernel<<<(Bb * Tt) / 8, 256>>>(x, abias);
    gemm_eln_kernel<<<ROWS / 16, 128>>>(gat_W, gat_b, sn_g, sn_b);
    gx_kernel<<<dim3(ROWS / 32, 3), 256>>>(W_ih, b_ih);
    gru_kernel<<<Bb * Nn / 2, 384>>>(W_hh, b_hh, out);
    tln_kernel<<<ROWS / 8, 256>>>(out, tn_g, tn_b);
}